// round 13
// baseline (speedup 1.0000x reference)
#include <cuda_runtime.h>

// Problem constants
#define BB 8
#define CC 128
#define NN 131072
#define PP 128
#define DD 128

constexpr int T = 64;             // n-tile size
constexpr int CTAS_PER_B = 18;    // 8*18 = 144 CTAs = 1 wave on 148 SMs
constexpr int TILES = NN / T;     // 2048 tiles per batch

// Scratch (device globals: no allocation allowed)
__device__ float g_part[BB * CTAS_PER_B * PP * CC]; // per-CTA partial sums
__device__ float g_sum[BB * PP * CC];   // [b][p][c] segment sums
__device__ float g_cnt[BB * PP];        // [b][p] counts
__device__ float g_y1[BB * CC * PP];    // [b][d][p]
__device__ float g_y2[BB * CC * PP];
__device__ float g_y3[BB * CC * PP];
__device__ float g_stats[6 * 128];      // per layer: sum[128], sumsq[128]

__device__ __forceinline__ unsigned smem_u32(const void* p) {
    return (unsigned)__cvta_generic_to_shared(p);
}

// ---------------------------------------------------------------------------
// k_zero: clear count + stats accumulators (g_sum is overwritten by k_reduce)
// ---------------------------------------------------------------------------
__global__ void k_zero() {
    int i = blockIdx.x * 256 + threadIdx.x;
    if (i < BB * PP) g_cnt[i] = 0.f;
    if (i < 6 * 128) g_stats[i] = 0.f;
}

// ---------------------------------------------------------------------------
// k_count: label histogram -> g_cnt (float). 128 CTAs x 256 thr, 8192 labels each.
// ---------------------------------------------------------------------------
__global__ void k_count(const int* __restrict__ labels) {
    __shared__ int h[PP];
    int tid = threadIdx.x;
    if (tid < PP) h[tid] = 0;
    __syncthreads();
    int b = blockIdx.x >> 4;
    int off = (blockIdx.x & 15) * 8192;
    const int* lp = labels + (size_t)b * NN + off;
    for (int i = tid; i < 8192; i += 256) atomicAdd(&h[lp[i] & 127], 1);
    __syncthreads();
    if (tid < PP) atomicAdd(&g_cnt[b * PP + tid], (float)h[tid]);
}

// ---------------------------------------------------------------------------
// k_segsum: 256 threads (8 warps), dual parity-split accumulators.
//   - cp.async transposes [C=128][T=64] fp32 tiles into SMEM, swizzle
//     chunk' = q ^ (c&15): coalesced 512B global loads AND conflict-free
//     per-quad column reads (verified at LDS.128 4-phase granularity).
//   - warps 0-3 process even n-quads into acc0; warps 4-7 odd quads into
//     acc1. Warp w owns channels [32*(w&3), 32*(w&3)+32). Label uniform
//     across the warp per n -> lanes hit 32 distinct banks, no atomics.
//   - label masked &127 (labels in [0,128) by construction); bounds the
//     scatter to the acc region so ptxas can hoist tile loads past stores.
//   - partial acc0+acc1 stored coalesced to g_part (no global atomics);
//     k_reduce folds the 18 partials per batch.
// SMEM: 2x acc 64KB + 2x tile 32KB + 2x labels 256B = 197120 B (dynamic).
// ---------------------------------------------------------------------------
__global__ void __launch_bounds__(256, 1)
k_segsum(const float* __restrict__ feat, const int* __restrict__ labels) {
    extern __shared__ char smraw[];
    float* acc0  = (float*)smraw;                      // [P][C] even quads
    float* acc1  = (float*)(smraw + 65536);            // [P][C] odd quads
    float* tiles = (float*)(smraw + 131072);           // 2 x [C=128][T=64]
    int*   lab   = (int*)(smraw + 131072 + 65536);     // 2 x [T=64]

    int tid = threadIdx.x, w = tid >> 5, lane = tid & 31;
    int b = blockIdx.x / CTAS_PER_B;
    int slot = blockIdx.x % CTAS_PER_B;

    for (int i = tid; i < PP * CC; i += 256) { acc0[i] = 0.f; acc1[i] = 0.f; }
    __syncthreads();

    const float* fb = feat + (size_t)b * CC * NN;
    const int*   lb = labels + (size_t)b * NN;

    // per warp: 16 rows (c = 16w .. 16w+15), 8 cp.async per thread
    auto produce = [&](int t, int buf) {
        int n0 = t * T;
        float* tb = tiles + buf * (CC * T);
        int q = lane & 15;
#pragma unroll
        for (int i = 0; i < 8; ++i) {
            int c = w * 16 + i * 2 + (lane >> 4);
            const float* src = fb + (size_t)c * NN + n0 + q * 4;
            unsigned dst = smem_u32(tb + c * T + ((q ^ (c & 15)) << 2));
            asm volatile("cp.async.cg.shared.global [%0], [%1], 16;\n" ::"r"(dst), "l"(src));
        }
        if (w == 0 && lane < 16) {
            const int* ls = lb + n0 + lane * 4;
            unsigned dst = smem_u32(lab + buf * T + lane * 4);
            asm volatile("cp.async.cg.shared.global [%0], [%1], 16;\n" ::"r"(dst), "l"(ls));
        }
        asm volatile("cp.async.commit_group;\n");
    };

    // warps 0-3: even quads -> acc0 ; warps 4-7: odd quads -> acc1
    auto process = [&](int buf) {
        int par = w >> 2;
        float* myacc = par ? acc1 : acc0;
        int c = (w & 3) * 32 + lane;
        const float* trow = tiles + buf * (CC * T) + c * T;
        const int* lrow = lab + buf * T;
        int cs = c & 15;
#pragma unroll
        for (int j = 0; j < 8; ++j) {
            int qd = 2 * j + par;
            float4 v = *(const float4*)(trow + ((qd ^ cs) << 2));
            int4 l = *(const int4*)(lrow + (qd << 2));
            myacc[(l.x & 127) * CC + c] += v.x;
            myacc[(l.y & 127) * CC + c] += v.y;
            myacc[(l.z & 127) * CC + c] += v.z;
            myacc[(l.w & 127) * CC + c] += v.w;
        }
    };

    int k = 0;
    produce(slot, 0);
    for (int t = slot; t < TILES; t += CTAS_PER_B, ++k) {
        int tn = t + CTAS_PER_B;
        if (tn < TILES) {
            produce(tn, (k + 1) & 1);
            asm volatile("cp.async.wait_group 1;\n");
        } else {
            asm volatile("cp.async.wait_group 0;\n");
        }
        __syncthreads();
        process(k & 1);
        __syncthreads();
    }

    // coalesced partial flush: 64 floats per thread as float4
    float* dst = g_part + ((size_t)b * CTAS_PER_B + slot) * PP * CC;
    for (int i = tid * 4; i < PP * CC; i += 1024) {
        float4 a = *(const float4*)(acc0 + i);
        float4 c4 = *(const float4*)(acc1 + i);
        float4 r{a.x + c4.x, a.y + c4.y, a.z + c4.z, a.w + c4.w};
        *(float4*)(dst + i) = r;
    }
}

// ---------------------------------------------------------------------------
// k_reduce: g_sum[b][p][c] = sum_j g_part[b][j][p][c]. 512 CTAs x 256 thr.
// ---------------------------------------------------------------------------
__global__ void k_reduce() {
    int idx = blockIdx.x * 256 + threadIdx.x;       // < BB*PP*CC = 131072
    int b = idx >> 14;                               // / 16384
    int r = idx & 16383;
    const float* src = g_part + (size_t)b * CTAS_PER_B * PP * CC + r;
    float s = 0.f;
#pragma unroll
    for (int j = 0; j < CTAS_PER_B; ++j) s += src[j * PP * CC];
    g_sum[idx] = s;
}

// ---------------------------------------------------------------------------
// k_layer: fused (input transform) -> conv1x1 -> (+bias) -> write y + BN stats.
//   inSel = -1 : input = g_sum / max(g_cnt,1)   (pooled)
//   inSel = 0/1: input = relu(BN(g_y1/g_y2)) using g_stats[inSel]
//   outSel     : writes g_y{outSel+1} and accumulates g_stats[outSel]
// Grid: 32 CTAs = 8 batches x 4 p-blocks(32). 256 threads.
// SMEM: W 64KB + xs[128][33] 16.5KB = 82432 B (dynamic).
// ---------------------------------------------------------------------------
__device__ __forceinline__ float* buf_sel(int s) {
    return s == 0 ? g_y1 : (s == 1 ? g_y2 : g_y3);
}

__global__ void __launch_bounds__(256)
k_layer(const float* __restrict__ Wg, const float* __restrict__ bias,
        const float* __restrict__ gamma, const float* __restrict__ beta,
        int inSel, int outSel) {
    extern __shared__ float sm[];
    float* Wsm = sm;             // [128][128]
    float* xs = sm + 16384;      // [128][33] (padded vs bank conflicts)
    int tid = threadIdx.x;
    int b = blockIdx.x >> 2;
    int pb = (blockIdx.x & 3) * 32;

    for (int i = tid * 4; i < CC * CC; i += 1024)
        *(float4*)(Wsm + i) = *(const float4*)(Wg + i);

    if (inSel < 0) {
        int c = tid & 127, ph = tid >> 7;
        for (int pp = ph; pp < 32; pp += 2) {
            float cnt = g_cnt[b * PP + pb + pp];
            float val = g_sum[((size_t)b * PP + pb + pp) * CC + c];
            xs[c * 33 + pp] = val / fmaxf(cnt, 1.f);
        }
    } else {
        const float* s = g_stats + inSel * 256;
        const float* inY = buf_sel(inSel);
        int p = tid & 31, cg = tid >> 5;
        for (int c = cg; c < CC; c += 8) {
            float m = s[c] * (1.f / 1024.f);
            float var = s[128 + c] * (1.f / 1024.f) - m * m;
            float rs = rsqrtf(var + 1e-5f);
            float y = inY[((size_t)b * CC + c) * PP + pb + p];
            float xv = (y - m) * rs * gamma[c] + beta[c];
            xs[c * 33 + p] = fmaxf(xv, 0.f);
        }
    }
    __syncthreads();

    int w = tid >> 5, lane = tid & 31;
    int dbase = w * 16;
    float av[16];
#pragma unroll
    for (int j = 0; j < 16; ++j) av[j] = 0.f;
    for (int c = 0; c < CC; ++c) {
        float xv = xs[c * 33 + lane];
#pragma unroll
        for (int j = 0; j < 16; ++j) av[j] += Wsm[(dbase + j) * CC + c] * xv;
    }
    if (bias) {
#pragma unroll
        for (int j = 0; j < 16; ++j) av[j] += bias[dbase + j];
    }

    float* outY = buf_sel(outSel);
    float* so = g_stats + outSel * 256;
#pragma unroll
    for (int j = 0; j < 16; ++j) {
        int d = dbase + j;
        outY[((size_t)b * CC + d) * PP + pb + lane] = av[j];
        float s1 = av[j], s2 = av[j] * av[j];
#pragma unroll
        for (int o = 16; o; o >>= 1) {
            s1 += __shfl_xor_sync(0xffffffffu, s1, o);
            s2 += __shfl_xor_sync(0xffffffffu, s2, o);
        }
        if (lane == 0) {
            atomicAdd(&so[d], s1);
            atomicAdd(&so[128 + d], s2);
        }
    }
}

// ---------------------------------------------------------------------------
// k_final: BN3 (no relu) -> d_out, plus counts appended if the output expects it
// ---------------------------------------------------------------------------
__global__ void k_final(const float* __restrict__ g3v, const float* __restrict__ be3,
                        float* __restrict__ out, int out_size) {
    int i = blockIdx.x * 256 + threadIdx.x;
    if (i < BB * CC * PP) {
        int d = (i >> 7) & 127;
        const float* s = g_stats + 2 * 256;
        float m = s[d] * (1.f / 1024.f);
        float var = s[128 + d] * (1.f / 1024.f) - m * m;
        float rs = rsqrtf(var + 1e-5f);
        if (i < out_size) out[i] = (g_y3[i] - m) * rs * g3v[d] + be3[d];
    } else {
        int j = i - BB * CC * PP;
        if (j < BB * PP && i < out_size)
            out[i] = g_cnt[j];
    }
}

// ---------------------------------------------------------------------------
extern "C" void kernel_launch(void* const* d_in, const int* in_sizes, int n_in,
                              void* d_out, int out_size) {
    const float* feat  = (const float*)d_in[0];
    const int*   labels= (const int*)d_in[1];
    const float* W1 = (const float*)d_in[2];
    const float* b1 = (const float*)d_in[3];
    const float* g1 = (const float*)d_in[4];
    const float* be1= (const float*)d_in[5];
    const float* W2 = (const float*)d_in[6];
    const float* b2 = (const float*)d_in[7];
    const float* g2 = (const float*)d_in[8];
    const float* be2= (const float*)d_in[9];
    const float* W3 = (const float*)d_in[10];
    const float* g3 = (const float*)d_in[11];
    const float* be3= (const float*)d_in[12];
    float* out = (float*)d_out;

    cudaFuncSetAttribute(k_segsum, cudaFuncAttributeMaxDynamicSharedMemorySize, 197120);
    cudaFuncSetAttribute(k_layer, cudaFuncAttributeMaxDynamicSharedMemorySize, 82432);

    k_zero<<<4, 256>>>();
    k_count<<<128, 256>>>(labels);
    k_segsum<<<BB * CTAS_PER_B, 256, 197120>>>(feat, labels);
    k_reduce<<<512, 256>>>();
    k_layer<<<32, 256, 82432>>>(W1, b1, nullptr, nullptr, -1, 0);
    k_layer<<<32, 256, 82432>>>(W2, b2, g1, be1, 0, 1);
    k_layer<<<32, 256, 82432>>>(W3, nullptr, g2, be2, 1, 2);
    int tot = BB * CC * PP + BB * PP;
    k_final<<<(tot + 255) / 256, 256>>>(g3, be3, out, out_size);
}